// round 5
// baseline (speedup 1.0000x reference)
#include <cuda_runtime.h>
#include <math.h>

#define Cc   64
#define Hh   64
#define Ww   64
#define BSz  4
#define HS   256
#define WS   256
#define KK   8
#define NPH  16

// ---- device scratch (no allocations allowed) ----
__device__ float g_part[256];                         // per (b,ch) partial sums
__device__ __align__(16) float g_Wcm[4 * 2048];       // [pi][k][ch4][pj][4(ch%4)]
__device__ __align__(16) float g_Wem[4 * 2048];       // [pi][ch][k4][pj][4(k%4)]
__device__ __align__(16) float4 g_sampA[4 * 256];     // [pi][ch*4+pj]: {o0bits, w00, w01, w10}
__device__ float  g_sampB[4 * 256];                   // [pi][ch*4+pj]: w11
__device__ int2   g_sampYX[4 * 256];                  // [pi][ch*4+pj]: {Y0, X0}
__device__ int4   g_bnd[16];                          // [pi*4+pj]: {minY, maxY, minX, maxX}

// ---------------------------------------------------------------------------
// Kernel A: partial per-(b,ch) sums of x. grid=256, block=256.
// ---------------------------------------------------------------------------
__global__ void __launch_bounds__(256) mean_kernel(const float* __restrict__ x) {
    int bid = blockIdx.x;                // = b*64 + ch
    const float4* p = (const float4*)(x + (size_t)bid * 4096);
    float s = 0.f;
#pragma unroll
    for (int r = 0; r < 4; ++r) {
        float4 v = __ldg(p + r * 256 + threadIdx.x);
        s += (v.x + v.y) + (v.z + v.w);
    }
#pragma unroll
    for (int o = 16; o > 0; o >>= 1) s += __shfl_xor_sync(0xffffffffu, s, o);
    __shared__ float red[8];
    if ((threadIdx.x & 31) == 0) red[threadIdx.x >> 5] = s;
    __syncthreads();
    if (threadIdx.x == 0) {
        float tot = 0.f;
#pragma unroll
        for (int w = 0; w < 8; ++w) tot += red[w];
        g_part[bid] = tot;
    }
}

__device__ __forceinline__ float sigmoidf_(float v) { return 1.f / (1.f + expf(-v)); }

// stage a 64x64 row-major matrix into smem with pad-65 rows
__device__ __forceinline__ void stage65(float* sW, const float* __restrict__ W, int t) {
    const float4* W4 = (const float4*)W;
#pragma unroll
    for (int r = 0; r < 4; ++r) {
        float4 f = __ldg(W4 + r * 256 + t);
        int e0 = (r * 256 + t) * 4;
        int row = e0 >> 6, col = e0 & 63;
        float* d = sW + row * 65 + col;
        d[0] = f.x; d[1] = f.y; d[2] = f.z; d[3] = f.w;
    }
}

// ---------------------------------------------------------------------------
// Kernel B: per-phase meta network. 16 blocks x 256 threads.
// ---------------------------------------------------------------------------
__global__ void __launch_bounds__(256) phase_kernel(
    const float* __restrict__ wc,  const float* __restrict__ we,
    const float* __restrict__ Wb1, const float* __restrict__ bb1,
    const float* __restrict__ Wb2, const float* __restrict__ bb2,
    const float* __restrict__ Wr1, const float* __restrict__ br1,
    const float* __restrict__ Wr2, const float* __restrict__ br2,
    const float* __restrict__ Wq1, const float* __restrict__ bq1,
    const float* __restrict__ Wq2, const float* __restrict__ bq2,
    const float* __restrict__ Wq3, const float* __restrict__ bq3,
    const float* __restrict__ Wo1, const float* __restrict__ bo1,
    const float* __restrict__ Wo2, const float* __restrict__ bo2,
    const float* __restrict__ Wo3, const float* __restrict__ bo3)
{
    int p = blockIdx.x, pi = p >> 2, pj = p & 3;
    int t = threadIdx.x;  // 0..255
    float m2 = (pi + 0.5f) * 0.25f - 0.5f;
    float m3 = (pj + 0.5f) * 0.25f - 0.5f;

    __shared__ __align__(16) float sW[64 * 68];
    __shared__ __align__(16) float sU[64 * 68];
    __shared__ float s_mean[64];
    __shared__ __align__(16) float s_a[64][4];
    __shared__ __align__(16) float s_b[64][4];
    __shared__ float sWo1[256], bo1s[64], bo2s[64], sWo3[128];
    __shared__ float s_r[4], s_q1[64], s_q2[64], s_rw[4];
    __shared__ int s_bnd[4];

    if (t < 64)
        s_mean[t] = (g_part[t] + g_part[64 + t] + g_part[128 + t] + g_part[192 + t])
                    * (1.f / 16384.f);
    if (t == 0) { s_bnd[0] = 1000; s_bnd[1] = -1000; s_bnd[2] = 1000; s_bnd[3] = -1000; }

    // ---------- body layer 1 ----------
    stage65(sW, Wb1, t);
    __syncthreads();
    {
        int out = t >> 2, f = t & 3;
        float acc = 0.f;
        if (f == 0) {
#pragma unroll 8
            for (int ch = 0; ch < 64; ++ch) acc += sW[out * 65 + ch] * s_mean[ch];
        } else {
            float sr = 0.f;
#pragma unroll 8
            for (int ch = 0; ch < 64; ++ch) sr += sW[out * 65 + ch];
            acc = sr * ((f == 1) ? 0.25f : (f == 2) ? m2 : m3);
        }
        s_a[out][f] = fmaxf(acc + __ldg(bb1 + out), 0.f);
    }
    __syncthreads();

    // ---------- body layer 2 -> emb ----------
    stage65(sW, Wb2, t);
    __syncthreads();
    {
        int out = t >> 2, f = t & 3;
        float acc = __ldg(bb2 + out);
#pragma unroll 8
        for (int ch = 0; ch < 64; ++ch) acc += sW[out * 65 + ch] * s_a[ch][f];
        s_b[out][f] = fmaxf(acc, 0.f);
    }
    // ---------- offset head ----------
    if (t < 64) { bo1s[t] = __ldg(bo1 + t); bo2s[t] = __ldg(bo2 + t); }
    if (t >= 64 && t < 192) sWo3[t - 64] = __ldg(Wo3 + t - 64);
    if (t >= 192) { sWo1[t - 192] = __ldg(Wo1 + t - 192);
                    sWo1[t - 128] = __ldg(Wo1 + t - 128);
                    sWo1[t - 64]  = __ldg(Wo1 + t - 64);
                    sWo1[t]       = __ldg(Wo1 + t); }
    __syncthreads();
    {   // u1 transposed: sU[jn][ch], pad 68
        int ch = t & 63, g = t >> 6;
        float4 e = *(const float4*)&s_b[ch][0];
#pragma unroll
        for (int s = 0; s < 16; ++s) {
            int jn = g * 16 + s;
            float v = sWo1[jn * 4 + 0] * e.x + sWo1[jn * 4 + 1] * e.y +
                      sWo1[jn * 4 + 2] * e.z + sWo1[jn * 4 + 3] * e.w + bo1s[jn];
            sU[jn * 68 + ch] = fmaxf(v, 0.f);
        }
    }
    {   // stage Wo2 transposed: sW[i2*68 + jn] = Wo2[jn*64+i2]
        const float4* W4 = (const float4*)Wo2;
#pragma unroll
        for (int r = 0; r < 4; ++r) {
            float4 f = __ldg(W4 + r * 256 + t);
            int e0 = (r * 256 + t) * 4;
            int jn = e0 >> 6, i2 = e0 & 63;
            sW[(i2 + 0) * 68 + jn] = f.x;
            sW[(i2 + 1) * 68 + jn] = f.y;
            sW[(i2 + 2) * 68 + jn] = f.z;
            sW[(i2 + 3) * 68 + jn] = f.w;
        }
    }
    __syncthreads();
    float accg[4][4];
    {   // GEMM: u2 = relu(Wo2 @ u1 + bo2)
        int tc = t & 15, tj = t >> 4;
#pragma unroll
        for (int a = 0; a < 4; ++a)
#pragma unroll
            for (int bq = 0; bq < 4; ++bq) accg[a][bq] = 0.f;
#pragma unroll 8
        for (int i2 = 0; i2 < 64; ++i2) {
            float4 wv = *(const float4*)&sW[i2 * 68 + tj * 4];
            float4 uv = *(const float4*)&sU[i2 * 68 + tc * 4];
            accg[0][0] += wv.x * uv.x; accg[0][1] += wv.x * uv.y;
            accg[0][2] += wv.x * uv.z; accg[0][3] += wv.x * uv.w;
            accg[1][0] += wv.y * uv.x; accg[1][1] += wv.y * uv.y;
            accg[1][2] += wv.y * uv.z; accg[1][3] += wv.y * uv.w;
            accg[2][0] += wv.z * uv.x; accg[2][1] += wv.z * uv.y;
            accg[2][2] += wv.z * uv.z; accg[2][3] += wv.z * uv.w;
            accg[3][0] += wv.w * uv.x; accg[3][1] += wv.w * uv.y;
            accg[3][2] += wv.w * uv.z; accg[3][3] += wv.w * uv.w;
        }
    }
    __syncthreads();
    {
        int tc = t & 15, tj = t >> 4;
#pragma unroll
        for (int a = 0; a < 4; ++a) {
            float bv = bo2s[tj * 4 + a];
#pragma unroll
            for (int bq = 0; bq < 4; ++bq)
                sU[(tc * 4 + bq) * 68 + tj * 4 + a] = fmaxf(accg[a][bq] + bv, 0.f);
        }
    }
    __syncthreads();
    if (t < 64) {   // final 64->2 + sample constants
        float ox = __ldg(bo3 + 0), oy = __ldg(bo3 + 1);
#pragma unroll 8
        for (int jn = 0; jn < 64; ++jn) {
            float u = sU[t * 68 + jn];
            ox += sWo3[jn] * u;
            oy += sWo3[64 + jn] * u;
        }
        float cy = m2 + oy, cx = m3 + ox;
        float Y0 = floorf(cy), X0 = floorf(cx);
        float wy = cy - Y0, wx = cx - X0;
        float omy = 1.f - wy, omx = 1.f - wx;
        int Y0i = (int)Y0, X0i = (int)X0;
        g_sampA[pi * 256 + t * 4 + pj] =
            make_float4(__int_as_float(Y0i * Ww + X0i), omy * omx, omy * wx, wy * omx);
        g_sampB[pi * 256 + t * 4 + pj]  = wy * wx;
        g_sampYX[pi * 256 + t * 4 + pj] = make_int2(Y0i, X0i);
        atomicMin(&s_bnd[0], Y0i); atomicMax(&s_bnd[1], Y0i);
        atomicMin(&s_bnd[2], X0i); atomicMax(&s_bnd[3], X0i);
    }
    __syncthreads();
    if (t == 0)
        g_bnd[p] = make_int4(s_bnd[0], s_bnd[1], s_bnd[2], s_bnd[3]);

    // ---------- routing_1 ----------
    stage65(sW, Wr1, t);
    __syncthreads();
    {
        int out = t >> 2, f = t & 3;
        float acc = __ldg(br1 + out);
#pragma unroll 8
        for (int ch = 0; ch < 64; ++ch) acc += sW[out * 65 + ch] * s_b[ch][f];
        s_a[out][f] = fmaxf(acc, 0.f);
    }
    __syncthreads();
    if (t < 4) {
        float acc = __ldg(br2);
#pragma unroll 8
        for (int o = 0; o < 64; ++o) acc += __ldg(Wr2 + o) * s_a[o][t];
        s_r[t] = sigmoidf_(acc);
    }
    __syncthreads();
    if (t < 64) {
        float q = __ldg(bq1 + t);
#pragma unroll
        for (int f = 0; f < 4; ++f) q += __ldg(Wq1 + t * 4 + f) * s_r[f];
        s_q1[t] = fmaxf(q, 0.f);
    }
    stage65(sW, Wq2, t);
    __syncthreads();
    if (t < 64) {
        float q = __ldg(bq2 + t);
#pragma unroll 8
        for (int o = 0; o < 64; ++o) q += sW[t * 65 + o] * s_q1[o];
        s_q2[t] = fmaxf(q, 0.f);
    }
    __syncthreads();
    if (t < 4) {
        float acc = __ldg(bq3 + t);
#pragma unroll 8
        for (int o = 0; o < 64; ++o) acc += __ldg(Wq3 + t * 64 + o) * s_q2[o];
        s_rw[t] = sigmoidf_(acc);
    }
    __syncthreads();

    // ---------- expert-mixed compress/expand matrices ----------
    {
        float w0 = s_rw[0], w1 = s_rw[1], w2 = s_rw[2], w3 = s_rw[3];
        int ch = t & 63, kg = t >> 6;
#pragma unroll
        for (int kk = 0; kk < 2; ++kk) {
            int k = kg * 2 + kk;
            int gi = k * 64 + ch;
            g_Wcm[pi * 2048 + ((k * 16 + (ch >> 2)) * 4 + pj) * 4 + (ch & 3)] =
                w0 * __ldg(wc + gi)        + w1 * __ldg(wc + 512 + gi)
              + w2 * __ldg(wc + 1024 + gi) + w3 * __ldg(wc + 1536 + gi);
            int gj = ch * 8 + k;
            g_Wem[pi * 2048 + ((ch * 2 + (k >> 2)) * 4 + pj) * 4 + (k & 3)] =
                w0 * __ldg(we + gj)        + w1 * __ldg(we + 512 + gj)
              + w2 * __ldg(we + 1024 + gj) + w3 * __ldg(we + 1536 + gj);
        }
    }
}

// ---------------------------------------------------------------------------
// Kernel C: fused sample + per-pixel 64->8->64 matmul + residual.
// Fast path (interior pixels, ~90%): unpredicated gathers via precomputed
// fused offset o0 and 4 bilinear weights. Slow path: clamped + weight-masked.
// ---------------------------------------------------------------------------
__global__ void __launch_bounds__(256, 2) main_kernel(const float* __restrict__ x,
                                                      float* __restrict__ out)
{
    __shared__ float4 sWcm[512];     // [k][ch4][pj]
    __shared__ float4 sWem[512];     // [ch][k4][pj]
    __shared__ float4 sSampA[256];   // [ch][pj]: {o0bits, w00, w01, w10}
    __shared__ float  sSampB[256];   // [ch][pj]: w11
    __shared__ int2   sYX[256];      // [ch][pj]
    __shared__ int4   sBnd[4];       // per pj

    int pi  = blockIdx.y & 3;
    int tid = threadIdx.y * 32 + threadIdx.x;
    {
        const float4* gc = ((const float4*)g_Wcm) + pi * 512;
        const float4* ge = ((const float4*)g_Wem) + pi * 512;
        sWcm[tid]       = gc[tid];
        sWcm[tid + 256] = gc[tid + 256];
        sWem[tid]       = ge[tid];
        sWem[tid + 256] = ge[tid + 256];
        sSampA[tid] = g_sampA[pi * 256 + tid];
        sSampB[tid] = g_sampB[pi * 256 + tid];
        sYX[tid]    = g_sampYX[pi * 256 + tid];
        if (tid < 4) sBnd[tid] = g_bnd[pi * 4 + tid];
    }
    __syncthreads();

    int lane = threadIdx.x;
    int j  = blockIdx.x * 32 + lane;
    int pj = lane & 3;
    int sj = j >> 2;
    int si = (blockIdx.y >> 2) * 8 + threadIdx.y;
    int i  = si * 4 + pi;
    int b  = blockIdx.z;

    const float* xb = x + (size_t)b * (Cc * Hh * Ww);
    const float* pbase = xb + si * Ww + sj;

    int4 bd = sBnd[pj];
    bool fast = (si + bd.x >= 0) & (si + bd.y <= Hh - 2) &
                (sj + bd.z >= 0) & (sj + bd.w <= Ww - 2);

    float fea[64];
    if (fast) {
#pragma unroll
        for (int ch = 0; ch < 64; ++ch) {
            float4 sa = sSampA[ch * 4 + pj];
            float w11v = sSampB[ch * 4 + pj];
            const float* p = pbase + ch * (Hh * Ww) + __float_as_int(sa.x);
            float g00 = __ldg(p);
            float g01 = __ldg(p + 1);
            float g10 = __ldg(p + Ww);
            float g11 = __ldg(p + Ww + 1);
            fea[ch] = g00 * sa.y + g01 * sa.z + g10 * sa.w + g11 * w11v;
        }
    } else {
#pragma unroll 1
        for (int ch = 0; ch < 64; ++ch) {
            float4 sa = sSampA[ch * 4 + pj];
            float w11v = sSampB[ch * 4 + pj];
            int2 yx = sYX[ch * 4 + pj];
            int iy = si + yx.x, ix = sj + yx.y;
            bool vy0 = ((unsigned)iy       < (unsigned)Hh);
            bool vy1 = ((unsigned)(iy + 1) < (unsigned)Hh);
            bool vx0 = ((unsigned)ix       < (unsigned)Ww);
            bool vx1 = ((unsigned)(ix + 1) < (unsigned)Ww);
            int iy0 = min(max(iy, 0), Hh - 1), iy1 = min(max(iy + 1, 0), Hh - 1);
            int ix0 = min(max(ix, 0), Ww - 1), ix1 = min(max(ix + 1, 0), Ww - 1);
            const float* img = xb + ch * (Hh * Ww);
            float g00 = __ldg(img + iy0 * Ww + ix0);
            float g01 = __ldg(img + iy0 * Ww + ix1);
            float g10 = __ldg(img + iy1 * Ww + ix0);
            float g11 = __ldg(img + iy1 * Ww + ix1);
            fea[ch] = g00 * ((vy0 & vx0) ? sa.y : 0.f)
                    + g01 * ((vy0 & vx1) ? sa.z : 0.f)
                    + g10 * ((vy1 & vx0) ? sa.w : 0.f)
                    + g11 * ((vy1 & vx1) ? w11v : 0.f);
        }
    }

    float mid[KK];
#pragma unroll
    for (int k = 0; k < KK; ++k) {
        float acc = 0.f;
#pragma unroll
        for (int c4 = 0; c4 < 16; ++c4) {
            float4 w = sWcm[(k * 16 + c4) * 4 + pj];
            acc += w.x * fea[4 * c4]     + w.y * fea[4 * c4 + 1]
                 + w.z * fea[4 * c4 + 2] + w.w * fea[4 * c4 + 3];
        }
        mid[k] = acc;
    }

    float* op = out + (size_t)b * (Cc * HS * WS) + i * WS + j;
#pragma unroll
    for (int ch = 0; ch < 64; ++ch) {
        float4 wa = sWem[(ch * 2 + 0) * 4 + pj];
        float4 wb = sWem[(ch * 2 + 1) * 4 + pj];
        float acc = fea[ch];
        acc += wa.x * mid[0] + wa.y * mid[1] + wa.z * mid[2] + wa.w * mid[3];
        acc += wb.x * mid[4] + wb.y * mid[5] + wb.z * mid[6] + wb.w * mid[7];
        op[(size_t)ch * (HS * WS)] = acc;
    }
}

// ---------------------------------------------------------------------------
extern "C" void kernel_launch(void* const* d_in, const int* in_sizes, int n_in,
                              void* d_out, int out_size) {
    const float* x   = (const float*)d_in[0];
    const float* wc  = (const float*)d_in[1];
    const float* we  = (const float*)d_in[2];
    const float* Wb1 = (const float*)d_in[3];
    const float* bb1 = (const float*)d_in[4];
    const float* Wb2 = (const float*)d_in[5];
    const float* bb2 = (const float*)d_in[6];
    const float* Wr1 = (const float*)d_in[7];
    const float* br1 = (const float*)d_in[8];
    const float* Wr2 = (const float*)d_in[9];
    const float* br2 = (const float*)d_in[10];
    const float* Wq1 = (const float*)d_in[11];
    const float* bq1 = (const float*)d_in[12];
    const float* Wq2 = (const float*)d_in[13];
    const float* bq2 = (const float*)d_in[14];
    const float* Wq3 = (const float*)d_in[15];
    const float* bq3 = (const float*)d_in[16];
    const float* Wo1 = (const float*)d_in[17];
    const float* bo1 = (const float*)d_in[18];
    const float* Wo2 = (const float*)d_in[19];
    const float* bo2 = (const float*)d_in[20];
    const float* Wo3 = (const float*)d_in[21];
    const float* bo3 = (const float*)d_in[22];
    // d_in[23] = scale (4)

    mean_kernel<<<256, 256>>>(x);
    phase_kernel<<<NPH, 256>>>(wc, we, Wb1, bb1, Wb2, bb2, Wr1, br1, Wr2, br2,
                               Wq1, bq1, Wq2, bq2, Wq3, bq3,
                               Wo1, bo1, Wo2, bo2, Wo3, bo3);
    dim3 grid(WS / 32, 32, BSz);   // 8 x 32 x 4 = 1024 blocks
    main_kernel<<<grid, dim3(32, 8)>>>(x, (float*)d_out);
}

// round 8
// speedup vs baseline: 1.7214x; 1.7214x over previous
#include <cuda_runtime.h>
#include <math.h>

#define Cc   64
#define Hh   64
#define Ww   64
#define BSz  4
#define HS   256
#define WS   256
#define KK   8
#define NPH  16

// ---- device scratch (no allocations allowed) ----
__device__ float g_part[256];                         // per (b,ch) partial sums
__device__ __align__(16) float g_Wcm[4 * 2048];       // [pi][k][ch4][pj][4(ch%4)]
__device__ __align__(16) float g_Wem[4 * 2048];       // [pi][ch][k4][pj][4(k%4)]
__device__ __align__(16) float4 g_sampA[4 * 256];     // [pi][ch*4+pj]: {o0bits, w00, w01, w10}
__device__ float  g_sampB[4 * 256];                   // [pi][ch*4+pj]: w11
__device__ int2   g_sampYX[4 * 256];                  // [pi][ch*4+pj]: {Y0, X0}
__device__ int4   g_bnd[16];                          // [pi*4+pj]: {minY, maxY, minX, maxX}

// ---------------------------------------------------------------------------
// Kernel A: partial per-(b,ch) sums of x. grid=256, block=256.
// ---------------------------------------------------------------------------
__global__ void __launch_bounds__(256) mean_kernel(const float* __restrict__ x) {
    int bid = blockIdx.x;                // = b*64 + ch
    const float4* p = (const float4*)(x + (size_t)bid * 4096);
    float s = 0.f;
#pragma unroll
    for (int r = 0; r < 4; ++r) {
        float4 v = __ldg(p + r * 256 + threadIdx.x);
        s += (v.x + v.y) + (v.z + v.w);
    }
#pragma unroll
    for (int o = 16; o > 0; o >>= 1) s += __shfl_xor_sync(0xffffffffu, s, o);
    __shared__ float red[8];
    if ((threadIdx.x & 31) == 0) red[threadIdx.x >> 5] = s;
    __syncthreads();
    if (threadIdx.x == 0) {
        float tot = 0.f;
#pragma unroll
        for (int w = 0; w < 8; ++w) tot += red[w];
        g_part[bid] = tot;
    }
}

__device__ __forceinline__ float sigmoidf_(float v) { return 1.f / (1.f + expf(-v)); }

// stage a 64x64 row-major matrix into smem with pad-65 rows
__device__ __forceinline__ void stage65(float* sW, const float* __restrict__ W, int t) {
    const float4* W4 = (const float4*)W;
#pragma unroll
    for (int r = 0; r < 4; ++r) {
        float4 f = __ldg(W4 + r * 256 + t);
        int e0 = (r * 256 + t) * 4;
        int row = e0 >> 6, col = e0 & 63;
        float* d = sW + row * 65 + col;
        d[0] = f.x; d[1] = f.y; d[2] = f.z; d[3] = f.w;
    }
}

// ---------------------------------------------------------------------------
// Kernel B: per-phase meta network. 16 blocks x 256 threads.
// ---------------------------------------------------------------------------
__global__ void __launch_bounds__(256) phase_kernel(
    const float* __restrict__ wc,  const float* __restrict__ we,
    const float* __restrict__ Wb1, const float* __restrict__ bb1,
    const float* __restrict__ Wb2, const float* __restrict__ bb2,
    const float* __restrict__ Wr1, const float* __restrict__ br1,
    const float* __restrict__ Wr2, const float* __restrict__ br2,
    const float* __restrict__ Wq1, const float* __restrict__ bq1,
    const float* __restrict__ Wq2, const float* __restrict__ bq2,
    const float* __restrict__ Wq3, const float* __restrict__ bq3,
    const float* __restrict__ Wo1, const float* __restrict__ bo1,
    const float* __restrict__ Wo2, const float* __restrict__ bo2,
    const float* __restrict__ Wo3, const float* __restrict__ bo3)
{
    int p = blockIdx.x, pi = p >> 2, pj = p & 3;
    int t = threadIdx.x;  // 0..255
    float m2 = (pi + 0.5f) * 0.25f - 0.5f;
    float m3 = (pj + 0.5f) * 0.25f - 0.5f;

    __shared__ __align__(16) float sW[64 * 68];
    __shared__ __align__(16) float sU[64 * 68];
    __shared__ float s_mean[64];
    __shared__ __align__(16) float s_a[64][4];
    __shared__ __align__(16) float s_b[64][4];
    __shared__ float sWo1[256], bo1s[64], bo2s[64], sWo3[128];
    __shared__ float s_r[4], s_q1[64], s_q2[64], s_rw[4];
    __shared__ int s_bnd[4];

    if (t < 64)
        s_mean[t] = (g_part[t] + g_part[64 + t] + g_part[128 + t] + g_part[192 + t])
                    * (1.f / 16384.f);
    if (t == 0) { s_bnd[0] = 1000; s_bnd[1] = -1000; s_bnd[2] = 1000; s_bnd[3] = -1000; }

    // ---------- body layer 1 ----------
    stage65(sW, Wb1, t);
    __syncthreads();
    {
        int out = t >> 2, f = t & 3;
        float acc = 0.f;
        if (f == 0) {
#pragma unroll 8
            for (int ch = 0; ch < 64; ++ch) acc += sW[out * 65 + ch] * s_mean[ch];
        } else {
            float sr = 0.f;
#pragma unroll 8
            for (int ch = 0; ch < 64; ++ch) sr += sW[out * 65 + ch];
            acc = sr * ((f == 1) ? 0.25f : (f == 2) ? m2 : m3);
        }
        s_a[out][f] = fmaxf(acc + __ldg(bb1 + out), 0.f);
    }
    __syncthreads();

    // ---------- body layer 2 -> emb ----------
    stage65(sW, Wb2, t);
    __syncthreads();
    {
        int out = t >> 2, f = t & 3;
        float acc = __ldg(bb2 + out);
#pragma unroll 8
        for (int ch = 0; ch < 64; ++ch) acc += sW[out * 65 + ch] * s_a[ch][f];
        s_b[out][f] = fmaxf(acc, 0.f);
    }
    // ---------- offset head ----------
    if (t < 64) { bo1s[t] = __ldg(bo1 + t); bo2s[t] = __ldg(bo2 + t); }
    if (t >= 64 && t < 192) sWo3[t - 64] = __ldg(Wo3 + t - 64);
    if (t >= 192) { sWo1[t - 192] = __ldg(Wo1 + t - 192);
                    sWo1[t - 128] = __ldg(Wo1 + t - 128);
                    sWo1[t - 64]  = __ldg(Wo1 + t - 64);
                    sWo1[t]       = __ldg(Wo1 + t); }
    __syncthreads();
    {   // u1 transposed: sU[jn][ch], pad 68
        int ch = t & 63, g = t >> 6;
        float4 e = *(const float4*)&s_b[ch][0];
#pragma unroll
        for (int s = 0; s < 16; ++s) {
            int jn = g * 16 + s;
            float v = sWo1[jn * 4 + 0] * e.x + sWo1[jn * 4 + 1] * e.y +
                      sWo1[jn * 4 + 2] * e.z + sWo1[jn * 4 + 3] * e.w + bo1s[jn];
            sU[jn * 68 + ch] = fmaxf(v, 0.f);
        }
    }
    {   // stage Wo2 transposed: sW[i2*68 + jn] = Wo2[jn*64+i2]
        const float4* W4 = (const float4*)Wo2;
#pragma unroll
        for (int r = 0; r < 4; ++r) {
            float4 f = __ldg(W4 + r * 256 + t);
            int e0 = (r * 256 + t) * 4;
            int jn = e0 >> 6, i2 = e0 & 63;
            sW[(i2 + 0) * 68 + jn] = f.x;
            sW[(i2 + 1) * 68 + jn] = f.y;
            sW[(i2 + 2) * 68 + jn] = f.z;
            sW[(i2 + 3) * 68 + jn] = f.w;
        }
    }
    __syncthreads();
    float accg[4][4];
    {   // GEMM: u2 = relu(Wo2 @ u1 + bo2)
        int tc = t & 15, tj = t >> 4;
#pragma unroll
        for (int a = 0; a < 4; ++a)
#pragma unroll
            for (int bq = 0; bq < 4; ++bq) accg[a][bq] = 0.f;
#pragma unroll 8
        for (int i2 = 0; i2 < 64; ++i2) {
            float4 wv = *(const float4*)&sW[i2 * 68 + tj * 4];
            float4 uv = *(const float4*)&sU[i2 * 68 + tc * 4];
            accg[0][0] += wv.x * uv.x; accg[0][1] += wv.x * uv.y;
            accg[0][2] += wv.x * uv.z; accg[0][3] += wv.x * uv.w;
            accg[1][0] += wv.y * uv.x; accg[1][1] += wv.y * uv.y;
            accg[1][2] += wv.y * uv.z; accg[1][3] += wv.y * uv.w;
            accg[2][0] += wv.z * uv.x; accg[2][1] += wv.z * uv.y;
            accg[2][2] += wv.z * uv.z; accg[2][3] += wv.z * uv.w;
            accg[3][0] += wv.w * uv.x; accg[3][1] += wv.w * uv.y;
            accg[3][2] += wv.w * uv.z; accg[3][3] += wv.w * uv.w;
        }
    }
    __syncthreads();
    {
        int tc = t & 15, tj = t >> 4;
#pragma unroll
        for (int a = 0; a < 4; ++a) {
            float bv = bo2s[tj * 4 + a];
#pragma unroll
            for (int bq = 0; bq < 4; ++bq)
                sU[(tc * 4 + bq) * 68 + tj * 4 + a] = fmaxf(accg[a][bq] + bv, 0.f);
        }
    }
    __syncthreads();
    if (t < 64) {   // final 64->2 + sample constants
        float ox = __ldg(bo3 + 0), oy = __ldg(bo3 + 1);
#pragma unroll 8
        for (int jn = 0; jn < 64; ++jn) {
            float u = sU[t * 68 + jn];
            ox += sWo3[jn] * u;
            oy += sWo3[64 + jn] * u;
        }
        float cy = m2 + oy, cx = m3 + ox;
        float Y0 = floorf(cy), X0 = floorf(cx);
        float wy = cy - Y0, wx = cx - X0;
        float omy = 1.f - wy, omx = 1.f - wx;
        int Y0i = (int)Y0, X0i = (int)X0;
        g_sampA[pi * 256 + t * 4 + pj] =
            make_float4(__int_as_float(Y0i * Ww + X0i), omy * omx, omy * wx, wy * omx);
        g_sampB[pi * 256 + t * 4 + pj]  = wy * wx;
        g_sampYX[pi * 256 + t * 4 + pj] = make_int2(Y0i, X0i);
        atomicMin(&s_bnd[0], Y0i); atomicMax(&s_bnd[1], Y0i);
        atomicMin(&s_bnd[2], X0i); atomicMax(&s_bnd[3], X0i);
    }
    __syncthreads();
    if (t == 0)
        g_bnd[p] = make_int4(s_bnd[0], s_bnd[1], s_bnd[2], s_bnd[3]);

    // ---------- routing_1 ----------
    stage65(sW, Wr1, t);
    __syncthreads();
    {
        int out = t >> 2, f = t & 3;
        float acc = __ldg(br1 + out);
#pragma unroll 8
        for (int ch = 0; ch < 64; ++ch) acc += sW[out * 65 + ch] * s_b[ch][f];
        s_a[out][f] = fmaxf(acc, 0.f);
    }
    __syncthreads();
    if (t < 4) {
        float acc = __ldg(br2);
#pragma unroll 8
        for (int o = 0; o < 64; ++o) acc += __ldg(Wr2 + o) * s_a[o][t];
        s_r[t] = sigmoidf_(acc);
    }
    __syncthreads();
    if (t < 64) {
        float q = __ldg(bq1 + t);
#pragma unroll
        for (int f = 0; f < 4; ++f) q += __ldg(Wq1 + t * 4 + f) * s_r[f];
        s_q1[t] = fmaxf(q, 0.f);
    }
    stage65(sW, Wq2, t);
    __syncthreads();
    if (t < 64) {
        float q = __ldg(bq2 + t);
#pragma unroll 8
        for (int o = 0; o < 64; ++o) q += sW[t * 65 + o] * s_q1[o];
        s_q2[t] = fmaxf(q, 0.f);
    }
    __syncthreads();
    if (t < 4) {
        float acc = __ldg(bq3 + t);
#pragma unroll 8
        for (int o = 0; o < 64; ++o) acc += __ldg(Wq3 + t * 64 + o) * s_q2[o];
        s_rw[t] = sigmoidf_(acc);
    }
    __syncthreads();

    // ---------- expert-mixed compress/expand matrices ----------
    {
        float w0 = s_rw[0], w1 = s_rw[1], w2 = s_rw[2], w3 = s_rw[3];
        int ch = t & 63, kg = t >> 6;
#pragma unroll
        for (int kk = 0; kk < 2; ++kk) {
            int k = kg * 2 + kk;
            int gi = k * 64 + ch;
            g_Wcm[pi * 2048 + ((k * 16 + (ch >> 2)) * 4 + pj) * 4 + (ch & 3)] =
                w0 * __ldg(wc + gi)        + w1 * __ldg(wc + 512 + gi)
              + w2 * __ldg(wc + 1024 + gi) + w3 * __ldg(wc + 1536 + gi);
            int gj = ch * 8 + k;
            g_Wem[pi * 2048 + ((ch * 2 + (k >> 2)) * 4 + pj) * 4 + (k & 3)] =
                w0 * __ldg(we + gj)        + w1 * __ldg(we + 512 + gj)
              + w2 * __ldg(we + 1024 + gj) + w3 * __ldg(we + 1536 + gj);
        }
    }
}

// ---------------------------------------------------------------------------
// Kernel C: fused sample + per-pixel 64->8->64 matmul + residual.
// Both gather paths FULLY UNROLLED (static fea indexing -> registers).
// Fast/slow selection is block+row uniform (bounds combined over all pj).
// ---------------------------------------------------------------------------
__global__ void __launch_bounds__(256, 2) main_kernel(const float* __restrict__ x,
                                                      float* __restrict__ out)
{
    __shared__ float4 sWcm[512];     // [k][ch4][pj]
    __shared__ float4 sWem[512];     // [ch][k4][pj]
    __shared__ float4 sSampA[256];   // [ch][pj]: {o0bits, w00, w01, w10}
    __shared__ float  sSampB[256];   // [ch][pj]: w11
    __shared__ int2   sYX[256];      // [ch][pj]
    __shared__ int4   sBndAll;       // combined over pj

    int pi  = blockIdx.y & 3;
    int tid = threadIdx.y * 32 + threadIdx.x;
    {
        const float4* gc = ((const float4*)g_Wcm) + pi * 512;
        const float4* ge = ((const float4*)g_Wem) + pi * 512;
        sWcm[tid]       = gc[tid];
        sWcm[tid + 256] = gc[tid + 256];
        sWem[tid]       = ge[tid];
        sWem[tid + 256] = ge[tid + 256];
        sSampA[tid] = g_sampA[pi * 256 + tid];
        sSampB[tid] = g_sampB[pi * 256 + tid];
        sYX[tid]    = g_sampYX[pi * 256 + tid];
        if (tid == 0) {
            int4 r = g_bnd[pi * 4 + 0];
#pragma unroll
            for (int q = 1; q < 4; ++q) {
                int4 c = g_bnd[pi * 4 + q];
                r.x = min(r.x, c.x); r.y = max(r.y, c.y);
                r.z = min(r.z, c.z); r.w = max(r.w, c.w);
            }
            sBndAll = r;
        }
    }
    __syncthreads();

    int lane = threadIdx.x;
    int j  = blockIdx.x * 32 + lane;
    int pj = lane & 3;
    int sj = j >> 2;
    int sj0 = blockIdx.x * 8;        // sj range of this block: [sj0, sj0+7]
    int si = (blockIdx.y >> 2) * 8 + threadIdx.y;
    int i  = si * 4 + pi;
    int b  = blockIdx.z;

    const float* xb = x + (size_t)b * (Cc * Hh * Ww);
    const float* pbase = xb + si * Ww + sj;

    int4 bd = sBndAll;
    bool fast = (si + bd.x >= 0) & (si + bd.y <= Hh - 2) &
                (sj0 + bd.z >= 0) & (sj0 + 7 + bd.w <= Ww - 2);

    float fea[64];
    if (fast) {
#pragma unroll
        for (int ch = 0; ch < 64; ++ch) {
            float4 sa = sSampA[ch * 4 + pj];
            float w11v = sSampB[ch * 4 + pj];
            const float* p = pbase + ch * (Hh * Ww) + __float_as_int(sa.x);
            float g00 = __ldg(p);
            float g01 = __ldg(p + 1);
            float g10 = __ldg(p + Ww);
            float g11 = __ldg(p + Ww + 1);
            fea[ch] = g00 * sa.y + g01 * sa.z + g10 * sa.w + g11 * w11v;
        }
    } else {
#pragma unroll
        for (int ch = 0; ch < 64; ++ch) {
            float4 sa = sSampA[ch * 4 + pj];
            float w11v = sSampB[ch * 4 + pj];
            int2 yx = sYX[ch * 4 + pj];
            int iy = si + yx.x, ix = sj + yx.y;
            bool vy0 = ((unsigned)iy       < (unsigned)Hh);
            bool vy1 = ((unsigned)(iy + 1) < (unsigned)Hh);
            bool vx0 = ((unsigned)ix       < (unsigned)Ww);
            bool vx1 = ((unsigned)(ix + 1) < (unsigned)Ww);
            int iy0 = min(max(iy, 0), Hh - 1), iy1 = min(max(iy + 1, 0), Hh - 1);
            int ix0 = min(max(ix, 0), Ww - 1), ix1 = min(max(ix + 1, 0), Ww - 1);
            const float* img = xb + ch * (Hh * Ww);
            float g00 = __ldg(img + iy0 * Ww + ix0);
            float g01 = __ldg(img + iy0 * Ww + ix1);
            float g10 = __ldg(img + iy1 * Ww + ix0);
            float g11 = __ldg(img + iy1 * Ww + ix1);
            fea[ch] = g00 * ((vy0 & vx0) ? sa.y : 0.f)
                    + g01 * ((vy0 & vx1) ? sa.z : 0.f)
                    + g10 * ((vy1 & vx0) ? sa.w : 0.f)
                    + g11 * ((vy1 & vx1) ? w11v : 0.f);
        }
    }

    float mid[KK];
#pragma unroll
    for (int k = 0; k < KK; ++k) {
        float acc = 0.f;
#pragma unroll
        for (int c4 = 0; c4 < 16; ++c4) {
            float4 w = sWcm[(k * 16 + c4) * 4 + pj];
            acc += w.x * fea[4 * c4]     + w.y * fea[4 * c4 + 1]
                 + w.z * fea[4 * c4 + 2] + w.w * fea[4 * c4 + 3];
        }
        mid[k] = acc;
    }

    float* op = out + (size_t)b * (Cc * HS * WS) + i * WS + j;
#pragma unroll
    for (int ch = 0; ch < 64; ++ch) {
        float4 wa = sWem[(ch * 2 + 0) * 4 + pj];
        float4 wb = sWem[(ch * 2 + 1) * 4 + pj];
        float acc = fea[ch];
        acc += wa.x * mid[0] + wa.y * mid[1] + wa.z * mid[2] + wa.w * mid[3];
        acc += wb.x * mid[4] + wb.y * mid[5] + wb.z * mid[6] + wb.w * mid[7];
        op[(size_t)ch * (HS * WS)] = acc;
    }
}

// ---------------------------------------------------------------------------
extern "C" void kernel_launch(void* const* d_in, const int* in_sizes, int n_in,
                              void* d_out, int out_size) {
    const float* x   = (const float*)d_in[0];
    const float* wc  = (const float*)d_in[1];
    const float* we  = (const float*)d_in[2];
    const float* Wb1 = (const float*)d_in[3];
    const float* bb1 = (const float*)d_in[4];
    const float* Wb2 = (const float*)d_in[5];
    const float* bb2 = (const float*)d_in[6];
    const float* Wr1 = (const float*)d_in[7];
    const float* br1 = (const float*)d_in[8];
    const float* Wr2 = (const float*)d_in[9];
    const float* br2 = (const float*)d_in[10];
    const float* Wq1 = (const float*)d_in[11];
    const float* bq1 = (const float*)d_in[12];
    const float* Wq2 = (const float*)d_in[13];
    const float* bq2 = (const float*)d_in[14];
    const float* Wq3 = (const float*)d_in[15];
    const float* bq3 = (const float*)d_in[16];
    const float* Wo1 = (const float*)d_in[17];
    const float* bo1 = (const float*)d_in[18];
    const float* Wo2 = (const float*)d_in[19];
    const float* bo2 = (const float*)d_in[20];
    const float* Wo3 = (const float*)d_in[21];
    const float* bo3 = (const float*)d_in[22];
    // d_in[23] = scale (4)

    mean_kernel<<<256, 256>>>(x);
    phase_kernel<<<NPH, 256>>>(wc, we, Wb1, bb1, Wb2, bb2, Wr1, br1, Wr2, br2,
                               Wq1, bq1, Wq2, bq2, Wq3, bq3,
                               Wo1, bo1, Wo2, bo2, Wo3, bo3);
    dim3 grid(WS / 32, 32, BSz);   // 8 x 32 x 4 = 1024 blocks
    main_kernel<<<grid, dim3(32, 8)>>>(x, (float*)d_out);
}